// round 14
// baseline (speedup 1.0000x reference)
#include <cuda_runtime.h>
#include <cstdint>
#include <cstdio>

#define B_   8
#define C_   768
#define L_   4096
#define NH_  12
#define D_   64
#define BH_  (B_*NH_)
#define NC_  64                 // chunks per sequence
#define NT_  (BH_*NC_)          // 6144 chunk tasks
#define SPAD 136
#define DP   72                 // mma smem row pad
#define PADW 136                // solve rhs row pad (128 cols + 8)

// ---------------- scratch ----------------
__device__ float g_q[(size_t)B_ * C_ * L_];
__device__ float g_k[(size_t)B_ * C_ * L_];
__device__ float g_v[(size_t)B_ * C_ * L_];
__device__ float g_o[(size_t)B_ * C_ * L_];
__device__ float g_beta[(size_t)BH_ * L_];
// WY-representation per (bh,chunk): 64x64 each
__device__ float g_XT[(size_t)NT_ * 4096];   // X^T [d][i]
__device__ float g_Y [(size_t)NT_ * 4096];   // Y   [i][e]
__device__ float g_Pt[(size_t)NT_ * 4096];   // P^T [d][d']
__device__ float g_R [(size_t)NT_ * 4096];   // R   [d'][e]
__device__ float g_S [(size_t)NT_ * 4096];   // S_c [d][e]

__device__ __forceinline__ uint32_t f2tf(float f) {
    uint32_t r;
    asm("cvt.rna.tf32.f32 %0, %1;" : "=r"(r) : "f"(f));
    return r;
}
__device__ __forceinline__ float tfbits(float f) {
    return __uint_as_float(f2tf(f));
}
__device__ __forceinline__ void mma_tf32(float c[4], const uint32_t a[4], const uint32_t b[2]) {
    asm volatile(
        "mma.sync.aligned.m16n8k8.row.col.f32.tf32.tf32.f32 "
        "{%0,%1,%2,%3}, {%4,%5,%6,%7}, {%8,%9}, {%0,%1,%2,%3};"
        : "+f"(c[0]), "+f"(c[1]), "+f"(c[2]), "+f"(c[3])
        : "r"(a[0]), "r"(a[1]), "r"(a[2]), "r"(a[3]), "r"(b[0]), "r"(b[1]));
}

// ---------------- tf32 tensor-core GEMM (validated; unchanged) ----------------
template<int EPI, int NZ>
__global__ __launch_bounds__(256) void gemm_tf32(
    const float* __restrict__ A,
    const float* __restrict__ W0, const float* __restrict__ W1, const float* __restrict__ W2,
    const float* __restrict__ R,
    float* __restrict__ O0, float* __restrict__ O1, float* __restrict__ O2)
{
    __shared__ uint32_t As[2][16][SPAD];
    __shared__ uint32_t Bs[2][16][SPAD];

    const int tid  = threadIdx.x;
    const int wid  = tid >> 5;
    const int lane = tid & 31;
    const int m0   = blockIdx.x * 128;
    const int b    = m0 >> 12;
    const int l0   = m0 & 4095;
    const int n0   = blockIdx.y * 128;

    const float* W;
    float* Out;
    if (NZ > 1) {
        const int z = blockIdx.z;
        W   = (z == 0) ? W0 : (z == 1) ? W1 : W2;
        Out = (z == 0) ? O0 : (z == 1) ? O1 : O2;
    } else {
        W = W0; Out = O0;
    }
    const float* Ab = A + (size_t)b * C_ * L_ + l0;

    const int lk = tid >> 5;
    const int lc = (tid & 31) << 2;

    const int wm = (wid & 3) * 32;
    const int wn = (wid >> 2) * 64;
    const int g  = lane >> 2;
    const int tg = lane & 3;

    float acc[2][8][4];
#pragma unroll
    for (int mf = 0; mf < 2; mf++)
#pragma unroll
        for (int j = 0; j < 8; j++)
#pragma unroll
            for (int r = 0; r < 4; r++) acc[mf][j][r] = 0.f;

    float4 pa0, pa1, pw0, pw1;
    pa0 = *(const float4*)(Ab + (size_t)lk * L_ + lc);
    pa1 = *(const float4*)(Ab + (size_t)(lk + 8) * L_ + lc);
    pw0 = *(const float4*)(W + (size_t)lk * C_ + n0 + lc);
    pw1 = *(const float4*)(W + (size_t)(lk + 8) * C_ + n0 + lc);
    {
        uint4 u;
        u.x = f2tf(pa0.x); u.y = f2tf(pa0.y); u.z = f2tf(pa0.z); u.w = f2tf(pa0.w);
        *(uint4*)&As[0][lk][lc] = u;
        u.x = f2tf(pa1.x); u.y = f2tf(pa1.y); u.z = f2tf(pa1.z); u.w = f2tf(pa1.w);
        *(uint4*)&As[0][lk + 8][lc] = u;
        u.x = f2tf(pw0.x); u.y = f2tf(pw0.y); u.z = f2tf(pw0.z); u.w = f2tf(pw0.w);
        *(uint4*)&Bs[0][lk][lc] = u;
        u.x = f2tf(pw1.x); u.y = f2tf(pw1.y); u.z = f2tf(pw1.z); u.w = f2tf(pw1.w);
        *(uint4*)&Bs[0][lk + 8][lc] = u;
    }
    __syncthreads();

    for (int k0 = 0; k0 < C_; k0 += 16) {
        const int  buf  = (k0 >> 4) & 1;
        const bool more = (k0 + 16) < C_;
        if (more) {
            pa0 = *(const float4*)(Ab + (size_t)(k0 + 16 + lk) * L_ + lc);
            pa1 = *(const float4*)(Ab + (size_t)(k0 + 24 + lk) * L_ + lc);
            pw0 = *(const float4*)(W + (size_t)(k0 + 16 + lk) * C_ + n0 + lc);
            pw1 = *(const float4*)(W + (size_t)(k0 + 24 + lk) * C_ + n0 + lc);
        }
#pragma unroll
        for (int ks = 0; ks < 16; ks += 8) {
            uint32_t af[2][4], bf[8][2];
#pragma unroll
            for (int mf = 0; mf < 2; mf++) {
                const int mr = wm + mf * 16 + g;
                af[mf][0] = As[buf][ks + tg][mr];
                af[mf][1] = As[buf][ks + tg][mr + 8];
                af[mf][2] = As[buf][ks + 4 + tg][mr];
                af[mf][3] = As[buf][ks + 4 + tg][mr + 8];
            }
#pragma unroll
            for (int j = 0; j < 8; j++) {
                const int nc = wn + j * 8 + g;
                bf[j][0] = Bs[buf][ks + tg][nc];
                bf[j][1] = Bs[buf][ks + 4 + tg][nc];
            }
#pragma unroll
            for (int mf = 0; mf < 2; mf++)
#pragma unroll
                for (int j = 0; j < 8; j++)
                    mma_tf32(acc[mf][j], af[mf], bf[j]);
        }
        if (more) {
            uint4 u;
            u.x = f2tf(pa0.x); u.y = f2tf(pa0.y); u.z = f2tf(pa0.z); u.w = f2tf(pa0.w);
            *(uint4*)&As[buf ^ 1][lk][lc] = u;
            u.x = f2tf(pa1.x); u.y = f2tf(pa1.y); u.z = f2tf(pa1.z); u.w = f2tf(pa1.w);
            *(uint4*)&As[buf ^ 1][lk + 8][lc] = u;
            u.x = f2tf(pw0.x); u.y = f2tf(pw0.y); u.z = f2tf(pw0.z); u.w = f2tf(pw0.w);
            *(uint4*)&Bs[buf ^ 1][lk][lc] = u;
            u.x = f2tf(pw1.x); u.y = f2tf(pw1.y); u.z = f2tf(pw1.z); u.w = f2tf(pw1.w);
            *(uint4*)&Bs[buf ^ 1][lk + 8][lc] = u;
        }
        __syncthreads();
    }

    float* stage = (float*)&As[0][0][0];
#pragma unroll 1
    for (int s = 0; s < 4; s++) {
#pragma unroll
        for (int mf = 0; mf < 2; mf++)
#pragma unroll
            for (int j = 0; j < 8; j++) {
                if (((wn + j * 8) >> 5) != s) continue;
                const int n = (wn + j * 8 + tg * 2) & 31;
                const int m = wm + mf * 16 + g;
                float v0 = acc[mf][j][0], v1 = acc[mf][j][1];
                float v2 = acc[mf][j][2], v3 = acc[mf][j][3];
                if (EPI == 0) {
                    v0 = v0 / (1.f + __expf(-v0));
                    v1 = v1 / (1.f + __expf(-v1));
                    v2 = v2 / (1.f + __expf(-v2));
                    v3 = v3 / (1.f + __expf(-v3));
                }
                stage[n * 132 + m]           = v0;
                stage[(n + 1) * 132 + m]     = v1;
                stage[n * 132 + m + 8]       = v2;
                stage[(n + 1) * 132 + m + 8] = v3;
            }
        __syncthreads();
        {
            const int nr   = tid >> 3;
            const int lcol = (tid & 7) << 4;
            const size_t gb = ((size_t)(b * C_ + n0 + s * 32 + nr)) * L_ + l0 + lcol;
            float v[16];
#pragma unroll
            for (int t = 0; t < 16; t++) v[t] = stage[nr * 132 + lcol + t];
            if (EPI == 1) {
                const float* r = R + gb;
#pragma unroll
                for (int t = 0; t < 16; t++) v[t] += r[t];
            }
            float* dst = Out + gb;
            *(float4*)(dst)      = *(float4*)(v);
            *(float4*)(dst + 4)  = *(float4*)(v + 4);
            *(float4*)(dst + 8)  = *(float4*)(v + 8);
            *(float4*)(dst + 12) = *(float4*)(v + 12);
        }
        __syncthreads();
    }
}

// ---------------- beta = sigmoid(t @ Wb) ----------------
__global__ __launch_bounds__(256) void beta_kernel(
    const float* __restrict__ X, const float* __restrict__ Wb,
    float* __restrict__ Beta)
{
    __shared__ float As[16][256];
    __shared__ float Ws[16][12];
    const int tid = threadIdx.x;
    const int m0  = blockIdx.x * 256;
    const int b   = m0 >> 12;
    const int l0  = m0 & 4095;
    const float* Ab = X + (size_t)b * C_ * L_ + l0;

    float acc[12];
#pragma unroll
    for (int h = 0; h < 12; h++) acc[h] = 0.f;

    for (int k0 = 0; k0 < C_; k0 += 16) {
#pragma unroll
        for (int kk = 0; kk < 16; kk++) As[kk][tid] = Ab[(size_t)(k0 + kk) * L_ + tid];
        if (tid < 192) Ws[tid / 12][tid % 12] = Wb[(size_t)(k0 + tid / 12) * 12 + (tid % 12)];
        __syncthreads();
#pragma unroll
        for (int kk = 0; kk < 16; kk++) {
            float a = As[kk][tid];
#pragma unroll
            for (int h = 0; h < 12; h++) acc[h] += a * Ws[kk][h];
        }
        __syncthreads();
    }
#pragma unroll
    for (int h = 0; h < 12; h++) {
        Beta[((size_t)(b * NH_ + h)) * L_ + l0 + tid] = 1.f / (1.f + __expf(-acc[h]));
    }
}

// ================= Phase 1: per-chunk WY build (fully parallel) =================
// Solve via per-block triangular inversion + split-tf32 mma (no scalar FS updates).
__global__ __launch_bounds__(256) void p1_kernel(
    const float* __restrict__ gk, const float* __restrict__ gv,
    const float* __restrict__ gb,
    float* __restrict__ gXT, float* __restrict__ gY,
    float* __restrict__ gPt, float* __restrict__ gR)
{
    extern __shared__ float sm[];
    float* k_t  = sm;                // [d][i] tf32 (normalized k)
    float* kr_t = k_t  + 64 * DP;    // [i][d] tf32
    float* Wt_f = kr_t + 64 * DP;    // [j][i] fp32: W^T (W = I + tril(beta*KK^T))
    float* XY   = Wt_f + 64 * DP;    // [i][0:128) rhs -> solved (fp32)
    float* Li   = XY   + 64 * PADW;  // [jl][blk*16+il] fp32: Linv_blk[il][jl] (4 blocks)
    float* bv   = Li   + 16 * DP;    // [64]

    const int tid  = threadIdx.x;
    const int wid  = tid >> 5;
    const int lane = tid & 31;
    const int wm = (wid & 3) * 16, wn = (wid >> 2) * 32;
    const int g  = lane >> 2,      tg = lane & 3;
    const int i0 = wm + g, i1 = wm + g + 8;

    const int task = blockIdx.x;
    const int bh = task >> 6, c = task & 63;
    const int b = bh / NH_, h = bh % NH_;
    const size_t base = ((size_t)(b * C_ + h * D_)) * L_ + c * 64;
    const float* kgp = gk + base;
    const float* vgp = gv + base;
    const float* bgp = gb + (size_t)bh * L_ + c * 64;
    const size_t toff = (size_t)task * 4096;

    const int ld  = tid >> 2;
    const int li0 = (tid & 3) << 4;

    // ---- A: load k [d][i] raw; v transposed into XY[i][64+e]; beta ----
    {
        const float* krow = kgp + (size_t)ld * L_ + li0;
        const float* vrow = vgp + (size_t)ld * L_ + li0;
#pragma unroll
        for (int u = 0; u < 16; u += 4) {
            float4 kv = *(const float4*)(krow + u);
            float4 vv = *(const float4*)(vrow + u);
            *(float4*)&k_t[ld * DP + li0 + u] = kv;
            XY[(li0 + u + 0) * PADW + 64 + ld] = vv.x;
            XY[(li0 + u + 1) * PADW + 64 + ld] = vv.y;
            XY[(li0 + u + 2) * PADW + 64 + ld] = vv.z;
            XY[(li0 + u + 3) * PADW + 64 + ld] = vv.w;
        }
        if (tid < 64) bv[tid] = bgp[tid];
    }
    __syncthreads();

    // ---- B: l2norm k; tf32 k_t/kr_t; X rhs = beta*k_norm; Y *= beta ----
    {
        const int tok = tid >> 2;
        const int d0  = (tid & 3) << 4;
        float sk = 0.f;
#pragma unroll
        for (int d = d0; d < d0 + 16; d++) {
            float kv = k_t[d * DP + tok]; sk += kv * kv;
        }
        sk += __shfl_xor_sync(0xFFFFFFFFu, sk, 1);
        sk += __shfl_xor_sync(0xFFFFFFFFu, sk, 2);
        const float rk = rsqrtf(sk + 1e-6f);
        const float be = bv[tok];
#pragma unroll
        for (int d = d0; d < d0 + 16; d++) {
            float kn = k_t[d * DP + tok] * rk;
            float kb = tfbits(kn);
            k_t[d * DP + tok] = kb;
            kr_t[tok * DP + d] = kb;
            XY[tok * PADW + d] = be * kn;
            XY[tok * PADW + 64 + d] *= be;
        }
    }
    __syncthreads();

    // ---- C: K K^T mma -> W^T (fp32, [j][i]) ----
    {
        float aT[4][4];
#pragma unroll
        for (int jt = 0; jt < 4; jt++)
#pragma unroll
            for (int r = 0; r < 4; r++) aT[jt][r] = 0.f;
#pragma unroll
        for (int ks = 0; ks < 64; ks += 8) {
            uint32_t ak[4];
            ak[0] = __float_as_uint(k_t[(ks + tg) * DP + i0]);
            ak[1] = __float_as_uint(k_t[(ks + tg) * DP + i1]);
            ak[2] = __float_as_uint(k_t[(ks + 4 + tg) * DP + i0]);
            ak[3] = __float_as_uint(k_t[(ks + 4 + tg) * DP + i1]);
#pragma unroll
            for (int jt = 0; jt < 4; jt++) {
                const int nc = wn + jt * 8 + g;
                uint32_t bk[2];
                bk[0] = __float_as_uint(k_t[(ks + tg) * DP + nc]);
                bk[1] = __float_as_uint(k_t[(ks + 4 + tg) * DP + nc]);
                mma_tf32(aT[jt], ak, bk);
            }
        }
        const float b0 = bv[i0], b1 = bv[i1];
#pragma unroll
        for (int jt = 0; jt < 4; jt++) {
            const int jc = wn + jt * 8 + 2 * tg;
            Wt_f[(jc    ) * DP + i0] = (jc     < i0) ? b0 * aT[jt][0] : (jc     == i0 ? 1.f : 0.f);
            Wt_f[(jc + 1) * DP + i0] = (jc + 1 < i0) ? b0 * aT[jt][1] : (jc + 1 == i0 ? 1.f : 0.f);
            Wt_f[(jc    ) * DP + i1] = (jc     < i1) ? b1 * aT[jt][2] : (jc     == i1 ? 1.f : 0.f);
            Wt_f[(jc + 1) * DP + i1] = (jc + 1 < i1) ? b1 * aT[jt][3] : (jc + 1 == i1 ? 1.f : 0.f);
        }
    }
    __syncthreads();

    // ---- D1: invert the four 16x16 unit-lower diagonal blocks (parallel, fp32) ----
    // Li[jl*DP + blk*16 + il] = Linv_blk[il][jl]  (A-operand layout for apply mma)
    if (wid < 4 && lane < 16) {
        const int blk = wid, bs = blk * 16, cc = lane;
        const int lb = blk * 16;
        Li[cc * DP + lb + 0] = (cc == 0) ? 1.f : 0.f;
#pragma unroll 1
        for (int ii = 1; ii < 16; ii++) {
            float s = 0.f;
            for (int j = 0; j < ii; j++)
                s += Wt_f[(bs + j) * DP + bs + ii] * Li[cc * DP + lb + j];
            Li[cc * DP + lb + ii] = ((ii == cc) ? 1.f : 0.f) - s;
        }
    }
    __syncthreads();

    // ---- D2: solve via mma (warp-private 16-column slices; no CTA syncs) ----
    {
        const int colbase = wid * 16;
#pragma unroll 1
        for (int br = 0; br < 4; br++) {
            const int bs2 = br * 16;
            // update: Z = rhs - W[bs2.., 0:bs2] @ U   (split-tf32, 3-term)
            if (br > 0) {
                float accZ[2][4];
#pragma unroll
                for (int jt = 0; jt < 2; jt++)
#pragma unroll
                    for (int r = 0; r < 4; r++) accZ[jt][r] = 0.f;
#pragma unroll 1
                for (int ks = 0; ks < bs2; ks += 8) {
                    uint32_t ah[4], al[4];
                    {
                        float w0 = Wt_f[(ks + tg) * DP + bs2 + g];
                        float w1 = Wt_f[(ks + tg) * DP + bs2 + g + 8];
                        float w2 = Wt_f[(ks + 4 + tg) * DP + bs2 + g];
                        float w3 = Wt_f[(ks + 4 + tg) * DP + bs2 + g + 8];
                        ah[0] = f2tf(w0); al[0] = f2tf(w0 - __uint_as_float(ah[0]));
                        ah[1] = f2tf(w1); al[1] = f2tf(w1 - __uint_as_float(ah[1]));
                        ah[2] = f2tf(w2); al[2] = f2tf(w2 - __uint_as_float(ah[2]));
                        ah[3] = f2tf(w3); al[3] = f2tf(w3 - __uint_as_float(ah[3]));
                    }
#pragma unroll
                    for (int jt = 0; jt < 2; jt++) {
                        const int nc = colbase + jt * 8 + g;
                        float v0 = XY[(ks + tg) * PADW + nc];
                        float v1 = XY[(ks + 4 + tg) * PADW + nc];
                        uint32_t bhv[2], blv[2];
                        bhv[0] = f2tf(v0); blv[0] = f2tf(v0 - __uint_as_float(bhv[0]));
                        bhv[1] = f2tf(v1); blv[1] = f2tf(v1 - __uint_as_float(bhv[1]));
                        mma_tf32(accZ[jt], ah, bhv);
                        mma_tf32(accZ[jt], ah, blv);
                        mma_tf32(accZ[jt], al, bhv);
                    }
                }
#pragma unroll
                for (int jt = 0; jt < 2; jt++) {
                    const int jc = colbase + jt * 8 + 2 * tg;
                    XY[(bs2 + g) * PADW + jc]         -= accZ[jt][0];
                    XY[(bs2 + g) * PADW + jc + 1]     -= accZ[jt][1];
                    XY[(bs2 + g + 8) * PADW + jc]     -= accZ[jt][2];
                    XY[(bs2 + g + 8) * PADW + jc + 1] -= accZ[jt][3];
                }
                __syncwarp();
            }
            // apply: U = Linv_br @ Z   (split-tf32, 3-term)
            {
                float accU[2][4];
#pragma unroll
                for (int jt = 0; jt < 2; jt++)
#pragma unroll
                    for (int r = 0; r < 4; r++) accU[jt][r] = 0.f;
#pragma unroll
                for (int ks = 0; ks < 16; ks += 8) {
                    uint32_t ah[4], al[4];
                    {
                        float l0 = Li[(ks + tg) * DP + bs2 + g];
                        float l1 = Li[(ks + tg) * DP + bs2 + g + 8];
                        float l2 = Li[(ks + 4 + tg) * DP + bs2 + g];
                        float l3 = Li[(ks + 4 + tg) * DP + bs2 + g + 8];
                        ah[0] = f2tf(l0); al[0] = f2tf(l0 - __uint_as_float(ah[0]));
                        ah[1] = f2tf(l1); al[1] = f2tf(l1 - __uint_as_float(ah[1]));
                        ah[2] = f2tf(l2); al[2] = f2tf(l2 - __uint_as_float(ah[2]));
                        ah[3] = f2tf(l3); al[3] = f2tf(l3 - __uint_as_float(ah[3]));
                    }
#pragma unroll
                    for (int jt = 0; jt < 2; jt++) {
                        const int nc = colbase + jt * 8 + g;
                        float v0 = XY[(bs2 + ks + tg) * PADW + nc];
                        float v1 = XY[(bs2 + ks + 4 + tg) * PADW + nc];
                        uint32_t bhv[2], blv[2];
                        bhv[0] = f2tf(v0); blv[0] = f2tf(v0 - __uint_as_float(bhv[0]));
                        bhv[1] = f2tf(v1); blv[1] = f2tf(v1 - __uint_as_float(bhv[1]));
                        mma_tf32(accU[jt], ah, bhv);
                        mma_tf32(accU[jt], ah, blv);
                        mma_tf32(accU[jt], al, bhv);
                    }
                }
#pragma unroll
                for (int jt = 0; jt < 2; jt++) {
                    const int jc = colbase + jt * 8 + 2 * tg;
                    XY[(bs2 + g) * PADW + jc]         = accU[jt][0];
                    XY[(bs2 + g) * PADW + jc + 1]     = accU[jt][1];
                    XY[(bs2 + g + 8) * PADW + jc]     = accU[jt][2];
                    XY[(bs2 + g + 8) * PADW + jc + 1] = accU[jt][3];
                }
                __syncwarp();
            }
        }
    }
    __syncthreads();

    // ---- E: P^T = I - X^T K, R = K^T Y via mma; store all ----
    {
        float aP[4][4], aR[4][4];
#pragma unroll
        for (int jt = 0; jt < 4; jt++)
#pragma unroll
            for (int r = 0; r < 4; r++) { aP[jt][r] = 0.f; aR[jt][r] = 0.f; }
#pragma unroll
        for (int ks = 0; ks < 64; ks += 8) {
            uint32_t ak[4];
            ak[0] = __float_as_uint(kr_t[(ks + tg) * DP + i0]);
            ak[1] = __float_as_uint(kr_t[(ks + tg) * DP + i1]);
            ak[2] = __float_as_uint(kr_t[(ks + 4 + tg) * DP + i0]);
            ak[3] = __float_as_uint(kr_t[(ks + 4 + tg) * DP + i1]);
#pragma unroll
            for (int jt = 0; jt < 4; jt++) {
                const int nc = wn + jt * 8 + g;
                uint32_t bX[2], bY[2];
                bX[0] = f2tf(XY[(ks + tg) * PADW + nc]);
                bX[1] = f2tf(XY[(ks + 4 + tg) * PADW + nc]);
                bY[0] = f2tf(XY[(ks + tg) * PADW + 64 + nc]);
                bY[1] = f2tf(XY[(ks + 4 + tg) * PADW + 64 + nc]);
                mma_tf32(aP[jt], ak, bX);   // (K^T X)[d'][d2]
                mma_tf32(aR[jt], ak, bY);   // (K^T Y)[d'][e]
            }
        }
#pragma unroll
        for (int jt = 0; jt < 4; jt++) {
            const int jc = wn + jt * 8 + 2 * tg;
            gPt[toff + (size_t)(jc    ) * 64 + i0] = ((jc    ) == i0 ? 1.f : 0.f) - aP[jt][0];
            gPt[toff + (size_t)(jc + 1) * 64 + i0] = ((jc + 1) == i0 ? 1.f : 0.f) - aP[jt][1];
            gPt[toff + (size_t)(jc    ) * 64 + i1] = ((jc    ) == i1 ? 1.f : 0.f) - aP[jt][2];
            gPt[toff + (size_t)(jc + 1) * 64 + i1] = ((jc + 1) == i1 ? 1.f : 0.f) - aP[jt][3];
            float2 r0 = make_float2(aR[jt][0], aR[jt][1]);
            float2 r1 = make_float2(aR[jt][2], aR[jt][3]);
            *(float2*)&gR[toff + (size_t)i0 * 64 + jc] = r0;
            *(float2*)&gR[toff + (size_t)i1 * 64 + jc] = r1;
        }
    }
    // ---- store X^T [d][i] and Y [i][e] ----
    {
        const int d  = tid >> 2;
        const int s0 = (tid & 3) << 4;
#pragma unroll
        for (int u = 0; u < 16; u += 4) {
            float4 xv;
            xv.x = XY[(s0 + u + 0) * PADW + d];
            xv.y = XY[(s0 + u + 1) * PADW + d];
            xv.z = XY[(s0 + u + 2) * PADW + d];
            xv.w = XY[(s0 + u + 3) * PADW + d];
            *(float4*)&gXT[toff + (size_t)d * 64 + s0 + u] = xv;
            *(float4*)&gY[toff + (size_t)d * 64 + s0 + u] =
                *(float4*)&XY[d * PADW + 64 + s0 + u];
        }
    }
}

// ================= Phase 2: state scan (96 CTAs, split-tf32 mma) =================
__global__ __launch_bounds__(256) void p2_kernel(
    const float* __restrict__ gPt, const float* __restrict__ gR,
    float* __restrict__ gS)
{
    extern __shared__ float sm[];
    float* S_f = sm;
    float* Sh  = S_f + 64 * DP;
    float* Sl  = Sh  + 64 * DP;
    float* Ph  = Sl  + 64 * DP;
    float* Pl  = Ph  + 64 * DP;

    const int tid  = threadIdx.x;
    const int wid  = tid >> 5;
    const int lane = tid & 31;
    const int wm = (wid & 3) * 16, wn = (wid >> 2) * 32;
    const int g  = lane >> 2,      tg = lane & 3;
    const int i0 = wm + g, i1 = wm + g + 8;

    const int bh = blockIdx.x;
    const int ld  = tid >> 2;
    const int le0 = (tid & 3) << 4;

    for (int i = tid; i < 3 * 64 * DP; i += 256) S_f[i] = 0.f;
    __syncthreads();

    for (int c = 0; c < 64; c++) {
        const size_t toff = ((size_t)bh * 64 + c) * 4096;
#pragma unroll
        for (int u = 0; u < 16; u += 4)
            *(float4*)&gS[toff + (size_t)ld * 64 + le0 + u] = *(float4*)&S_f[ld * DP + le0 + u];
        if (c == 63) break;
#pragma unroll
        for (int u = 0; u < 16; u += 4) {
            float4 p = *(const float4*)&gPt[toff + (size_t)ld * 64 + le0 + u];
            float4 ph, pl;
            ph.x = tfbits(p.x); pl.x = tfbits(p.x - ph.x);
            ph.y = tfbits(p.y); pl.y = tfbits(p.y - ph.y);
            ph.z = tfbits(p.z); pl.z = tfbits(p.z - ph.z);
            ph.w = tfbits(p.w); pl.w = tfbits(p.w - ph.w);
            *(float4*)&Ph[ld * DP + le0 + u] = ph;
            *(float4*)&Pl[ld * DP + le0 + u] = pl;
        }
        __syncthreads();
        float aS[4][4];
#pragma unroll
        for (int jt = 0; jt < 4; jt++)
#pragma unroll
            for (int r = 0; r < 4; r++) aS[jt][r] = 0.f;
#pragma unroll
        for (int ks = 0; ks < 64; ks += 8) {
            uint32_t ah[4], al[4];
            ah[0] = __float_as_uint(Ph[(ks + tg) * DP + i0]);
            ah[1] = __float_as_uint(Ph[(ks + tg) * DP + i1]);
            ah[2] = __float_as_uint(Ph[(ks + 4 + tg) * DP + i0]);
            ah[3] = __float_as_uint(Ph[(ks + 4 + tg) * DP + i1]);
            al[0] = __float_as_uint(Pl[(ks + tg) * DP + i0]);
            al[1] = __float_as_uint(Pl[(ks + tg) * DP + i1]);
            al[2] = __float_as_uint(Pl[(ks + 4 + tg) * DP + i0]);
            al[3] = __float_as_uint(Pl[(ks + 4 + tg) * DP + i1]);
#pragma unroll
            for (int jt = 0; jt < 4; jt++) {
                const int nc = wn + jt * 8 + g;
                uint32_t bh2[2], bl2[2];
                bh2[0] = __float_as_uint(Sh[(ks + tg) * DP + nc]);
                bh2[1] = __float_as_uint(Sh[(ks + 4 + tg) * DP + nc]);
                bl2[0] = __float_as_uint(Sl[(ks + tg) * DP + nc]);
                bl2[1] = __float_as_uint(Sl[(ks + 4 + tg) * DP + nc]);
                mma_tf32(aS[jt], ah, bh2);
                mma_tf32(aS[jt], ah, bl2);
                mma_tf32(aS[jt], al, bh2);
            }
        }
        __syncthreads();
#pragma unroll
        for (int jt = 0; jt < 4; jt++) {
            const int jc = wn + jt * 8 + 2 * tg;
            float2 r0 = *(const float2*)&gR[toff + (size_t)i0 * 64 + jc];
            float2 r1 = *(const float2*)&gR[toff + (size_t)i1 * 64 + jc];
            float s00 = aS[jt][0] + r0.x, s01 = aS[jt][1] + r0.y;
            float s10 = aS[jt][2] + r1.x, s11 = aS[jt][3] + r1.y;
            S_f[i0 * DP + jc] = s00; Sh[i0 * DP + jc] = tfbits(s00);
            Sl[i0 * DP + jc] = tfbits(s00 - tfbits(s00));
            S_f[i0 * DP + jc + 1] = s01; Sh[i0 * DP + jc + 1] = tfbits(s01);
            Sl[i0 * DP + jc + 1] = tfbits(s01 - tfbits(s01));
            S_f[i1 * DP + jc] = s10; Sh[i1 * DP + jc] = tfbits(s10);
            Sl[i1 * DP + jc] = tfbits(s10 - tfbits(s10));
            S_f[i1 * DP + jc + 1] = s11; Sh[i1 * DP + jc + 1] = tfbits(s11);
            Sl[i1 * DP + jc + 1] = tfbits(s11 - tfbits(s11));
        }
        __syncthreads();
    }
}

// ================= Phase 3: per-chunk output (fully parallel) =================
__global__ __launch_bounds__(256) void p3_kernel(
    const float* __restrict__ gq, const float* __restrict__ gk,
    const float* __restrict__ gXT, const float* __restrict__ gYv,
    const float* __restrict__ gS, float* __restrict__ go)
{
    extern __shared__ float sm[];
    float* q_t  = sm;
    float* k_t  = q_t  + 64 * DP;
    float* S_t  = k_t  + 64 * DP;
    float* XT_s = S_t  + 64 * DP;
    float* U_t  = XT_s + 64 * DP;
    float* QK_t = U_t  + 64 * DP;

    const int tid  = threadIdx.x;
    const int wid  = tid >> 5;
    const int lane = tid & 31;
    const int wm = (wid & 3) * 16, wn = (wid >> 2) * 32;
    const int g  = lane >> 2,      tg = lane & 3;
    const int i0 = wm + g, i1 = wm + g + 8;

    const int task = blockIdx.x;
    const int bh = task >> 6, c = task & 63;
    const int b = bh / NH_, h = bh % NH_;
    const size_t base = ((size_t)(b * C_ + h * D_)) * L_ + c * 64;
    const float* qgp = gq + base;
    const float* kgp = gk + base;
    float* ogp = go + base;
    const size_t toff = (size_t)task * 4096;

    const int ld  = tid >> 2;
    const int li0 = (tid & 3) << 4;

    {
        const float* qrow = qgp + (size_t)ld * L_ + li0;
        const float* krow = kgp + (size_t)ld * L_ + li0;
#pragma unroll
        for (int u = 0; u < 16; u += 4) {
            *(float4*)&q_t[ld * DP + li0 + u] = *(const float4*)(qrow + u);
            *(float4*)&k_t[ld * DP + li0 + u] = *(const float4*)(krow + u);
            float4 sv = *(const float4*)&gS[toff + (size_t)ld * 64 + li0 + u];
            float4 xv = *(const float4*)&gXT[toff + (size_t)ld * 64 + li0 + u];
            sv.x = tfbits(sv.x); sv.y = tfbits(sv.y); sv.z = tfbits(sv.z); sv.w = tfbits(sv.w);
            xv.x = tfbits(xv.x); xv.y = tfbits(xv.y); xv.z = tfbits(xv.z); xv.w = tfbits(xv.w);
            *(float4*)&S_t[ld * DP + li0 + u]  = sv;
            *(float4*)&XT_s[ld * DP + li0 + u] = xv;
        }
    }
    __syncthreads();

    {
        const int tok = tid >> 2;
        const int d0  = (tid & 3) << 4;
        float sq = 0.f, sk = 0.f;
#pragma unroll
        for (int d = d0; d < d0 + 16; d++) {
            float qv = q_t[d * DP + tok]; sq += qv * qv;
            float kv = k_t[d * DP + tok]; sk += kv * kv;
        }
        sq += __shfl_xor_sync(0xFFFFFFFFu, sq, 1);
        sq += __shfl_xor_sync(0xFFFFFFFFu, sq, 2);
        sk += __shfl_xor_sync(0xFFFFFFFFu, sk, 1);
        sk += __shfl_xor_sync(0xFFFFFFFFu, sk, 2);
        const float rq = rsqrtf(sq + 1e-6f);
        const float rk = rsqrtf(sk + 1e-6f);
#pragma unroll
        for (int d = d0; d < d0 + 16; d++) {
            q_t[d * DP + tok] = tfbits(q_t[d * DP + tok] * rq);
            k_t[d * DP + tok] = tfbits(k_t[d * DP + tok] * rk);
        }
    }
    __syncthreads();

    {
        float aU[4][4], aQ[4][4];
#pragma unroll
        for (int jt = 0; jt < 4; jt++)
#pragma unroll
            for (int r = 0; r < 4; r++) { aU[jt][r] = 0.f; aQ[jt][r] = 0.f; }
#pragma unroll
        for (int ks = 0; ks < 64; ks += 8) {
            uint32_t ax[4], aq[4];
            ax[0] = __float_as_uint(XT_s[(ks + tg) * DP + i0]);
            ax[1] = __float_as_uint(XT_s[(ks + tg) * DP + i1]);
            ax[2] = __float_as_uint(XT_s[(ks + 4 + tg) * DP + i0]);
            ax[3] = __float_as_uint(XT_s[(ks + 4 + tg) * DP + i1]);
            aq[0] = __float_as_uint(q_t[(ks + tg) * DP + i0]);
            aq[1] = __float_as_uint(q_t[(ks + tg) * DP + i1]);
            aq[2] = __float_as_uint(q_t[(ks + 4 + tg) * DP + i0]);
            aq[3] = __float_as_uint(q_t[(ks + 4 + tg) * DP + i1]);
#pragma unroll
            for (int jt = 0; jt < 4; jt++) {
                const int nc = wn + jt * 8 + g;
                uint32_t bS[2], bk[2];
                bS[0] = __float_as_uint(S_t[(ks + tg) * DP + nc]);
                bS[1] = __float_as_uint(S_t[(ks + 4 + tg) * DP + nc]);
                bk[0] = __float_as_uint(k_t[(ks + tg) * DP + nc]);
                bk[1] = __float_as_uint(k_t[(ks + 4 + tg) * DP + nc]);
                mma_tf32(aU[jt], ax, bS);
                mma_tf32(aQ[jt], aq, bk);
            }
        }
#pragma unroll
        for (int jt = 0; jt < 4; jt++) {
            const int jc = wn + jt * 8 + 2 * tg;
            float2 y0 = *(const float2*)&gYv[toff + (size_t)i0 * 64 + jc];
            float2 y1 = *(const float2*)&gYv[toff + (size_t)i1 * 64 + jc];
            U_t[i0 * DP + jc]     = tfbits(y0.x - aU[jt][0]);
            U_t[i0 * DP + jc + 1] = tfbits(y0.y - aU[jt][1]);
            U_t[i1 * DP + jc]     = tfbits(y1.x - aU[jt][2]);
            U_t[i1 * DP + jc + 1] = tfbits(y1.y - aU[jt][3]);
            QK_t[jc * DP + i0]       = tfbits((jc     <= i0) ? aQ[jt][0] : 0.f);
            QK_t[(jc + 1) * DP + i0] = tfbits((jc + 1 <= i0) ? aQ[jt][1] : 0.f);
            QK_t[jc * DP + i1]       = tfbits((jc     <= i1) ? aQ[jt][2] : 0.f);
            QK_t[(jc + 1) * DP + i1] = tfbits((jc + 1 <= i1) ? aQ[jt][3] : 0.f);
        }
    }
    __syncthreads();

    {
        float aO[4][4];
#pragma unroll
        for (int jt = 0; jt < 4; jt++)
#pragma unroll
            for (int r = 0; r < 4; r++) aO[jt][r] = 0.f;
#pragma unroll
        for (int ks = 0; ks < 64; ks += 8) {
            uint32_t aq[4], a2[4];
            aq[0] = __float_as_uint(q_t[(ks + tg) * DP + i0]);
            aq[1] = __float_as_uint(q_t[(ks + tg) * DP + i1]);
            aq[2] = __float_as_uint(q_t[(ks + 4 + tg) * DP + i0]);
            aq[3] = __float_as_uint(q_t[(ks + 4 + tg) * DP + i1]);
            a2[0] = __float_as_uint(QK_t[(ks + tg) * DP + i0]);
            a2[1] = __float_as_uint(QK_t[(ks + tg) * DP + i1]);
            a2[2] = __float_as_uint(QK_t[(ks + 4 + tg) * DP + i0]);
            a2[3] = __float_as_uint(QK_t[(ks + 4 + tg) * DP + i1]);
#pragma unroll
            for (int jt = 0; jt < 4; jt++) {
                const int nc = wn + jt * 8 + g;
                uint32_t bS[2], bU[2];
                bS[0] = __float_as_uint(S_t[(ks + tg) * DP + nc]);
                bS[1] = __float_as_uint(S_t[(ks + 4 + tg) * DP + nc]);
                bU[0] = __float_as_uint(U_t[(ks + tg) * DP + nc]);
                bU[1] = __float_as_uint(U_t[(ks + 4 + tg) * DP + nc]);
                mma_tf32(aO[jt], aq, bS);
                mma_tf32(aO[jt], a2, bU);
            }
        }
        __syncthreads();
#pragma unroll
        for (int jt = 0; jt < 4; jt++) {
            const int ec = wn + jt * 8 + 2 * tg;
            k_t[ec * DP + i0]       = aO[jt][0];
            k_t[(ec + 1) * DP + i0] = aO[jt][1];
            k_t[ec * DP + i1]       = aO[jt][2];
            k_t[(ec + 1) * DP + i1] = aO[jt][3];
        }
    }
    __syncthreads();

    {
        float* dst = ogp + (size_t)ld * L_ + li0;
#pragma unroll
        for (int u = 0; u < 16; u += 4)
            *(float4*)(dst + u) = *(float4*)&k_t[ld * DP + li0 + u];
    }
}

// ---------------- launch ----------------
extern "C" void kernel_launch(void* const* d_in, const int* in_sizes, int n_in,
                              void* d_out, int out_size)
{
    const float* x  = (const float*)d_in[0];
    const float* Wq = (const float*)d_in[1];
    const float* Wk = (const float*)d_in[2];
    const float* Wv = (const float*)d_in[3];
    const float* Wb = (const float*)d_in[4];
    const float* Wo = (const float*)d_in[5];
    float* out = (float*)d_out;

    float *qp, *kp, *vp, *op, *bp, *xtp, *yp, *ptp, *rp, *sp;
    cudaGetSymbolAddress((void**)&qp, g_q);
    cudaGetSymbolAddress((void**)&kp, g_k);
    cudaGetSymbolAddress((void**)&vp, g_v);
    cudaGetSymbolAddress((void**)&op, g_o);
    cudaGetSymbolAddress((void**)&bp, g_beta);
    cudaGetSymbolAddress((void**)&xtp, g_XT);
    cudaGetSymbolAddress((void**)&yp, g_Y);
    cudaGetSymbolAddress((void**)&ptp, g_Pt);
    cudaGetSymbolAddress((void**)&rp, g_R);
    cudaGetSymbolAddress((void**)&sp, g_S);

    const int smemP1 = (3 * 64 * DP + 64 * PADW + 16 * DP + 64) * (int)sizeof(float);
    const int smemP2 = (5 * 64 * DP) * (int)sizeof(float);
    const int smemP3 = (6 * 64 * DP) * (int)sizeof(float);
    cudaFuncSetAttribute(p1_kernel, cudaFuncAttributeMaxDynamicSharedMemorySize, smemP1);
    cudaFuncSetAttribute(p2_kernel, cudaFuncAttributeMaxDynamicSharedMemorySize, smemP2);
    cudaFuncSetAttribute(p3_kernel, cudaFuncAttributeMaxDynamicSharedMemorySize, smemP3);

    dim3 blk(256);
    beta_kernel<<<128, blk>>>(x, Wb, bp);
    gemm_tf32<0, 2><<<dim3(256, 6, 2), blk>>>(x, Wq, Wk, nullptr, nullptr, qp, kp, nullptr);
    gemm_tf32<0, 1><<<dim3(256, 6, 1), blk>>>(x, Wv, nullptr, nullptr, nullptr, vp, nullptr, nullptr);
    p1_kernel<<<NT_, blk, smemP1>>>(kp, vp, bp, xtp, yp, ptp, rp);
    p2_kernel<<<BH_, blk, smemP2>>>(ptp, rp, sp);
    p3_kernel<<<NT_, blk, smemP3>>>(qp, kp, xtp, yp, sp, op);
    gemm_tf32<1, 1><<<dim3(256, 6, 1), blk>>>(op, Wo, nullptr, nullptr, x, out, nullptr, nullptr);
}

// round 15
// speedup vs baseline: 1.0009x; 1.0009x over previous
#include <cuda_runtime.h>
#include <cstdint>
#include <cstdio>

#define B_   8
#define C_   768
#define L_   4096
#define NH_  12
#define D_   64
#define BH_  (B_*NH_)
#define NC_  64                 // chunks per sequence
#define NT_  (BH_*NC_)          // 6144 chunk tasks
#define SPAD 136
#define DP   72                 // mma smem row pad
#define PADW 136                // solve rhs row pad (128 cols + 8)

// ---------------- scratch ----------------
__device__ float g_q[(size_t)B_ * C_ * L_];
__device__ float g_k[(size_t)B_ * C_ * L_];
__device__ float g_v[(size_t)B_ * C_ * L_];
__device__ float g_o[(size_t)B_ * C_ * L_];
__device__ float g_beta[(size_t)BH_ * L_];
// WY-representation per (bh,chunk): 64x64 each
__device__ float g_XT[(size_t)NT_ * 4096];   // X^T [d][i]
__device__ float g_Y [(size_t)NT_ * 4096];   // Y   [i][e]
__device__ float g_Pt[(size_t)NT_ * 4096];   // P^T [d][d']
__device__ float g_R [(size_t)NT_ * 4096];   // R   [d'][e]
__device__ float g_S [(size_t)NT_ * 4096];   // S_c [d][e]

__device__ __forceinline__ uint32_t f2tf(float f) {
    uint32_t r;
    asm("cvt.rna.tf32.f32 %0, %1;" : "=r"(r) : "f"(f));
    return r;
}
__device__ __forceinline__ float tfbits(float f) {
    return __uint_as_float(f2tf(f));
}
__device__ __forceinline__ void mma_tf32(float c[4], const uint32_t a[4], const uint32_t b[2]) {
    asm volatile(
        "mma.sync.aligned.m16n8k8.row.col.f32.tf32.tf32.f32 "
        "{%0,%1,%2,%3}, {%4,%5,%6,%7}, {%8,%9}, {%0,%1,%2,%3};"
        : "+f"(c[0]), "+f"(c[1]), "+f"(c[2]), "+f"(c[3])
        : "r"(a[0]), "r"(a[1]), "r"(a[2]), "r"(a[3]), "r"(b[0]), "r"(b[1]));
}

// ---------------- tf32 tensor-core GEMM (validated; unchanged) ----------------
template<int EPI, int NZ>
__global__ __launch_bounds__(256) void gemm_tf32(
    const float* __restrict__ A,
    const float* __restrict__ W0, const float* __restrict__ W1, const float* __restrict__ W2,
    const float* __restrict__ R,
    float* __restrict__ O0, float* __restrict__ O1, float* __restrict__ O2)
{
    __shared__ uint32_t As[2][16][SPAD];
    __shared__ uint32_t Bs[2][16][SPAD];

    const int tid  = threadIdx.x;
    const int wid  = tid >> 5;
    const int lane = tid & 31;
    const int m0   = blockIdx.x * 128;
    const int b    = m0 >> 12;
    const int l0   = m0 & 4095;
    const int n0   = blockIdx.y * 128;

    const float* W;
    float* Out;
    if (NZ > 1) {
        const int z = blockIdx.z;
        W   = (z == 0) ? W0 : (z == 1) ? W1 : W2;
        Out = (z == 0) ? O0 : (z == 1) ? O1 : O2;
    } else {
        W = W0; Out = O0;
    }
    const float* Ab = A + (size_t)b * C_ * L_ + l0;

    const int lk = tid >> 5;
    const int lc = (tid & 31) << 2;

    const int wm = (wid & 3) * 32;
    const int wn = (wid >> 2) * 64;
    const int g  = lane >> 2;
    const int tg = lane & 3;

    float acc[2][8][4];
#pragma unroll
    for (int mf = 0; mf < 2; mf++)
#pragma unroll
        for (int j = 0; j < 8; j++)
#pragma unroll
            for (int r = 0; r < 4; r++) acc[mf][j][r] = 0.f;

    float4 pa0, pa1, pw0, pw1;
    pa0 = *(const float4*)(Ab + (size_t)lk * L_ + lc);
    pa1 = *(const float4*)(Ab + (size_t)(lk + 8) * L_ + lc);
    pw0 = *(const float4*)(W + (size_t)lk * C_ + n0 + lc);
    pw1 = *(const float4*)(W + (size_t)(lk + 8) * C_ + n0 + lc);
    {
        uint4 u;
        u.x = f2tf(pa0.x); u.y = f2tf(pa0.y); u.z = f2tf(pa0.z); u.w = f2tf(pa0.w);
        *(uint4*)&As[0][lk][lc] = u;
        u.x = f2tf(pa1.x); u.y = f2tf(pa1.y); u.z = f2tf(pa1.z); u.w = f2tf(pa1.w);
        *(uint4*)&As[0][lk + 8][lc] = u;
        u.x = f2tf(pw0.x); u.y = f2tf(pw0.y); u.z = f2tf(pw0.z); u.w = f2tf(pw0.w);
        *(uint4*)&Bs[0][lk][lc] = u;
        u.x = f2tf(pw1.x); u.y = f2tf(pw1.y); u.z = f2tf(pw1.z); u.w = f2tf(pw1.w);
        *(uint4*)&Bs[0][lk + 8][lc] = u;
    }
    __syncthreads();

    for (int k0 = 0; k0 < C_; k0 += 16) {
        const int  buf  = (k0 >> 4) & 1;
        const bool more = (k0 + 16) < C_;
        if (more) {
            pa0 = *(const float4*)(Ab + (size_t)(k0 + 16 + lk) * L_ + lc);
            pa1 = *(const float4*)(Ab + (size_t)(k0 + 24 + lk) * L_ + lc);
            pw0 = *(const float4*)(W + (size_t)(k0 + 16 + lk) * C_ + n0 + lc);
            pw1 = *(const float4*)(W + (size_t)(k0 + 24 + lk) * C_ + n0 + lc);
        }
#pragma unroll
        for (int ks = 0; ks < 16; ks += 8) {
            uint32_t af[2][4], bf[8][2];
#pragma unroll
            for (int mf = 0; mf < 2; mf++) {
                const int mr = wm + mf * 16 + g;
                af[mf][0] = As[buf][ks + tg][mr];
                af[mf][1] = As[buf][ks + tg][mr + 8];
                af[mf][2] = As[buf][ks + 4 + tg][mr];
                af[mf][3] = As[buf][ks + 4 + tg][mr + 8];
            }
#pragma unroll
            for (int j = 0; j < 8; j++) {
                const int nc = wn + j * 8 + g;
                bf[j][0] = Bs[buf][ks + tg][nc];
                bf[j][1] = Bs[buf][ks + 4 + tg][nc];
            }
#pragma unroll
            for (int mf = 0; mf < 2; mf++)
#pragma unroll
                for (int j = 0; j < 8; j++)
                    mma_tf32(acc[mf][j], af[mf], bf[j]);
        }
        if (more) {
            uint4 u;
            u.x = f2tf(pa0.x); u.y = f2tf(pa0.y); u.z = f2tf(pa0.z); u.w = f2tf(pa0.w);
            *(uint4*)&As[buf ^ 1][lk][lc] = u;
            u.x = f2tf(pa1.x); u.y = f2tf(pa1.y); u.z = f2tf(pa1.z); u.w = f2tf(pa1.w);
            *(uint4*)&As[buf ^ 1][lk + 8][lc] = u;
            u.x = f2tf(pw0.x); u.y = f2tf(pw0.y); u.z = f2tf(pw0.z); u.w = f2tf(pw0.w);
            *(uint4*)&Bs[buf ^ 1][lk][lc] = u;
            u.x = f2tf(pw1.x); u.y = f2tf(pw1.y); u.z = f2tf(pw1.z); u.w = f2tf(pw1.w);
            *(uint4*)&Bs[buf ^ 1][lk + 8][lc] = u;
        }
        __syncthreads();
    }

    float* stage = (float*)&As[0][0][0];
#pragma unroll 1
    for (int s = 0; s < 4; s++) {
#pragma unroll
        for (int mf = 0; mf < 2; mf++)
#pragma unroll
            for (int j = 0; j < 8; j++) {
                if (((wn + j * 8) >> 5) != s) continue;
                const int n = (wn + j * 8 + tg * 2) & 31;
                const int m = wm + mf * 16 + g;
                float v0 = acc[mf][j][0], v1 = acc[mf][j][1];
                float v2 = acc[mf][j][2], v3 = acc[mf][j][3];
                if (EPI == 0) {
                    v0 = v0 / (1.f + __expf(-v0));
                    v1 = v1 / (1.f + __expf(-v1));
                    v2 = v2 / (1.f + __expf(-v2));
                    v3 = v3 / (1.f + __expf(-v3));
                }
                stage[n * 132 + m]           = v0;
                stage[(n + 1) * 132 + m]     = v1;
                stage[n * 132 + m + 8]       = v2;
                stage[(n + 1) * 132 + m + 8] = v3;
            }
        __syncthreads();
        {
            const int nr   = tid >> 3;
            const int lcol = (tid & 7) << 4;
            const size_t gb = ((size_t)(b * C_ + n0 + s * 32 + nr)) * L_ + l0 + lcol;
            float v[16];
#pragma unroll
            for (int t = 0; t < 16; t++) v[t] = stage[nr * 132 + lcol + t];
            if (EPI == 1) {
                const float* r = R + gb;
#pragma unroll
                for (int t = 0; t < 16; t++) v[t] += r[t];
            }
            float* dst = Out + gb;
            *(float4*)(dst)      = *(float4*)(v);
            *(float4*)(dst + 4)  = *(float4*)(v + 4);
            *(float4*)(dst + 8)  = *(float4*)(v + 8);
            *(float4*)(dst + 12) = *(float4*)(v + 12);
        }
        __syncthreads();
    }
}

// ---------------- beta = sigmoid(t @ Wb) ----------------
__global__ __launch_bounds__(256) void beta_kernel(
    const float* __restrict__ X, const float* __restrict__ Wb,
    float* __restrict__ Beta)
{
    __shared__ float As[16][256];
    __shared__ float Ws[16][12];
    const int tid = threadIdx.x;
    const int m0  = blockIdx.x * 256;
    const int b   = m0 >> 12;
    const int l0  = m0 & 4095;
    const float* Ab = X + (size_t)b * C_ * L_ + l0;

    float acc[12];
#pragma unroll
    for (int h = 0; h < 12; h++) acc[h] = 0.f;

    for (int k0 = 0; k0 < C_; k0 += 16) {
#pragma unroll
        for (int kk = 0; kk < 16; kk++) As[kk][tid] = Ab[(size_t)(k0 + kk) * L_ + tid];
        if (tid < 192) Ws[tid / 12][tid % 12] = Wb[(size_t)(k0 + tid / 12) * 12 + (tid % 12)];
        __syncthreads();
#pragma unroll
        for (int kk = 0; kk < 16; kk++) {
            float a = As[kk][tid];
#pragma unroll
            for (int h = 0; h < 12; h++) acc[h] += a * Ws[kk][h];
        }
        __syncthreads();
    }
#pragma unroll
    for (int h = 0; h < 12; h++) {
        Beta[((size_t)(b * NH_ + h)) * L_ + l0 + tid] = 1.f / (1.f + __expf(-acc[h]));
    }
}

// ================= Phase 1: per-chunk WY build (fully parallel) =================
// Solve via per-block triangular inversion + split-tf32 mma (no scalar FS updates).
__global__ __launch_bounds__(256) void p1_kernel(
    const float* __restrict__ gk, const float* __restrict__ gv,
    const float* __restrict__ gb,
    float* __restrict__ gXT, float* __restrict__ gY,
    float* __restrict__ gPt, float* __restrict__ gR)
{
    extern __shared__ float sm[];
    float* k_t  = sm;                // [d][i] tf32 (normalized k)
    float* kr_t = k_t  + 64 * DP;    // [i][d] tf32
    float* Wt_f = kr_t + 64 * DP;    // [j][i] fp32: W^T (W = I + tril(beta*KK^T))
    float* XY   = Wt_f + 64 * DP;    // [i][0:128) rhs -> solved (fp32)
    float* Li   = XY   + 64 * PADW;  // [jl][blk*16+il] fp32: Linv_blk[il][jl] (4 blocks)
    float* bv   = Li   + 16 * DP;    // [64]

    const int tid  = threadIdx.x;
    const int wid  = tid >> 5;
    const int lane = tid & 31;
    const int wm = (wid & 3) * 16, wn = (wid >> 2) * 32;
    const int g  = lane >> 2,      tg = lane & 3;
    const int i0 = wm + g, i1 = wm + g + 8;

    const int task = blockIdx.x;
    const int bh = task >> 6, c = task & 63;
    const int b = bh / NH_, h = bh % NH_;
    const size_t base = ((size_t)(b * C_ + h * D_)) * L_ + c * 64;
    const float* kgp = gk + base;
    const float* vgp = gv + base;
    const float* bgp = gb + (size_t)bh * L_ + c * 64;
    const size_t toff = (size_t)task * 4096;

    const int ld  = tid >> 2;
    const int li0 = (tid & 3) << 4;

    // ---- A: load k [d][i] raw; v transposed into XY[i][64+e]; beta ----
    {
        const float* krow = kgp + (size_t)ld * L_ + li0;
        const float* vrow = vgp + (size_t)ld * L_ + li0;
#pragma unroll
        for (int u = 0; u < 16; u += 4) {
            float4 kv = *(const float4*)(krow + u);
            float4 vv = *(const float4*)(vrow + u);
            *(float4*)&k_t[ld * DP + li0 + u] = kv;
            XY[(li0 + u + 0) * PADW + 64 + ld] = vv.x;
            XY[(li0 + u + 1) * PADW + 64 + ld] = vv.y;
            XY[(li0 + u + 2) * PADW + 64 + ld] = vv.z;
            XY[(li0 + u + 3) * PADW + 64 + ld] = vv.w;
        }
        if (tid < 64) bv[tid] = bgp[tid];
    }
    __syncthreads();

    // ---- B: l2norm k; tf32 k_t/kr_t; X rhs = beta*k_norm; Y *= beta ----
    {
        const int tok = tid >> 2;
        const int d0  = (tid & 3) << 4;
        float sk = 0.f;
#pragma unroll
        for (int d = d0; d < d0 + 16; d++) {
            float kv = k_t[d * DP + tok]; sk += kv * kv;
        }
        sk += __shfl_xor_sync(0xFFFFFFFFu, sk, 1);
        sk += __shfl_xor_sync(0xFFFFFFFFu, sk, 2);
        const float rk = rsqrtf(sk + 1e-6f);
        const float be = bv[tok];
#pragma unroll
        for (int d = d0; d < d0 + 16; d++) {
            float kn = k_t[d * DP + tok] * rk;
            float kb = tfbits(kn);
            k_t[d * DP + tok] = kb;
            kr_t[tok * DP + d] = kb;
            XY[tok * PADW + d] = be * kn;
            XY[tok * PADW + 64 + d] *= be;
        }
    }
    __syncthreads();

    // ---- C: K K^T mma -> W^T (fp32, [j][i]) ----
    {
        float aT[4][4];
#pragma unroll
        for (int jt = 0; jt < 4; jt++)
#pragma unroll
            for (int r = 0; r < 4; r++) aT[jt][r] = 0.f;
#pragma unroll
        for (int ks = 0; ks < 64; ks += 8) {
            uint32_t ak[4];
            ak[0] = __float_as_uint(k_t[(ks + tg) * DP + i0]);
            ak[1] = __float_as_uint(k_t[(ks + tg) * DP + i1]);
            ak[2] = __float_as_uint(k_t[(ks + 4 + tg) * DP + i0]);
            ak[3] = __float_as_uint(k_t[(ks + 4 + tg) * DP + i1]);
#pragma unroll
            for (int jt = 0; jt < 4; jt++) {
                const int nc = wn + jt * 8 + g;
                uint32_t bk[2];
                bk[0] = __float_as_uint(k_t[(ks + tg) * DP + nc]);
                bk[1] = __float_as_uint(k_t[(ks + 4 + tg) * DP + nc]);
                mma_tf32(aT[jt], ak, bk);
            }
        }
        const float b0 = bv[i0], b1 = bv[i1];
#pragma unroll
        for (int jt = 0; jt < 4; jt++) {
            const int jc = wn + jt * 8 + 2 * tg;
            Wt_f[(jc    ) * DP + i0] = (jc     < i0) ? b0 * aT[jt][0] : (jc     == i0 ? 1.f : 0.f);
            Wt_f[(jc + 1) * DP + i0] = (jc + 1 < i0) ? b0 * aT[jt][1] : (jc + 1 == i0 ? 1.f : 0.f);
            Wt_f[(jc    ) * DP + i1] = (jc     < i1) ? b1 * aT[jt][2] : (jc     == i1 ? 1.f : 0.f);
            Wt_f[(jc + 1) * DP + i1] = (jc + 1 < i1) ? b1 * aT[jt][3] : (jc + 1 == i1 ? 1.f : 0.f);
        }
    }
    __syncthreads();

    // ---- D1: invert the four 16x16 unit-lower diagonal blocks (parallel, fp32) ----
    // Li[jl*DP + blk*16 + il] = Linv_blk[il][jl]  (A-operand layout for apply mma)
    if (wid < 4 && lane < 16) {
        const int blk = wid, bs = blk * 16, cc = lane;
        const int lb = blk * 16;
        Li[cc * DP + lb + 0] = (cc == 0) ? 1.f : 0.f;
#pragma unroll 1
        for (int ii = 1; ii < 16; ii++) {
            float s = 0.f;
            for (int j = 0; j < ii; j++)
                s += Wt_f[(bs + j) * DP + bs + ii] * Li[cc * DP + lb + j];
            Li[cc * DP + lb + ii] = ((ii == cc) ? 1.f : 0.f) - s;
        }
    }
    __syncthreads();

    // ---- D2: solve via mma (warp-private 16-column slices; no CTA syncs) ----
    {
        const int colbase = wid * 16;
#pragma unroll 1
        for (int br = 0; br < 4; br++) {
            const int bs2 = br * 16;
            // update: Z = rhs - W[bs2.., 0:bs2] @ U   (split-tf32, 3-term)
            if (br > 0) {
                float accZ[2][4];
#pragma unroll
                for (int jt = 0; jt < 2; jt++)
#pragma unroll
                    for (int r = 0; r < 4; r++) accZ[jt][r] = 0.f;
#pragma unroll 1
                for (int ks = 0; ks < bs2; ks += 8) {
                    uint32_t ah[4], al[4];
                    {
                        float w0 = Wt_f[(ks + tg) * DP + bs2 + g];
                        float w1 = Wt_f[(ks + tg) * DP + bs2 + g + 8];
                        float w2 = Wt_f[(ks + 4 + tg) * DP + bs2 + g];
                        float w3 = Wt_f[(ks + 4 + tg) * DP + bs2 + g + 8];
                        ah[0] = f2tf(w0); al[0] = f2tf(w0 - __uint_as_float(ah[0]));
                        ah[1] = f2tf(w1); al[1] = f2tf(w1 - __uint_as_float(ah[1]));
                        ah[2] = f2tf(w2); al[2] = f2tf(w2 - __uint_as_float(ah[2]));
                        ah[3] = f2tf(w3); al[3] = f2tf(w3 - __uint_as_float(ah[3]));
                    }
#pragma unroll
                    for (int jt = 0; jt < 2; jt++) {
                        const int nc = colbase + jt * 8 + g;
                        float v0 = XY[(ks + tg) * PADW + nc];
                        float v1 = XY[(ks + 4 + tg) * PADW + nc];
                        uint32_t bhv[2], blv[2];
                        bhv[0] = f2tf(v0); blv[0] = f2tf(v0 - __uint_as_float(bhv[0]));
                        bhv[1] = f2tf(v1); blv[1] = f2tf(v1 - __uint_as_float(bhv[1]));
                        mma_tf32(accZ[jt], ah, bhv);
                        mma_tf32(accZ[jt], ah, blv);
                        mma_tf32(accZ[jt], al, bhv);
                    }
                }
#pragma unroll
                for (int jt = 0; jt < 2; jt++) {
                    const int jc = colbase + jt * 8 + 2 * tg;
                    XY[(bs2 + g) * PADW + jc]         -= accZ[jt][0];
                    XY[(bs2 + g) * PADW + jc + 1]     -= accZ[jt][1];
                    XY[(bs2 + g + 8) * PADW + jc]     -= accZ[jt][2];
                    XY[(bs2 + g + 8) * PADW + jc + 1] -= accZ[jt][3];
                }
                __syncwarp();
            }
            // apply: U = Linv_br @ Z   (split-tf32, 3-term)
            {
                float accU[2][4];
#pragma unroll
                for (int jt = 0; jt < 2; jt++)
#pragma unroll
                    for (int r = 0; r < 4; r++) accU[jt][r] = 0.f;
#pragma unroll
                for (int ks = 0; ks < 16; ks += 8) {
                    uint32_t ah[4], al[4];
                    {
                        float l0 = Li[(ks + tg) * DP + bs2 + g];
                        float l1 = Li[(ks + tg) * DP + bs2 + g + 8];
                        float l2 = Li[(ks + 4 + tg) * DP + bs2 + g];
                        float l3 = Li[(ks + 4 + tg) * DP + bs2 + g + 8];
                        ah[0] = f2tf(l0); al[0] = f2tf(l0 - __uint_as_float(ah[0]));
                        ah[1] = f2tf(l1); al[1] = f2tf(l1 - __uint_as_float(ah[1]));
                        ah[2] = f2tf(l2); al[2] = f2tf(l2 - __uint_as_float(ah[2]));
                        ah[3] = f2tf(l3); al[3] = f2tf(l3 - __uint_as_float(ah[3]));
                    }
#pragma unroll
                    for (int jt = 0; jt < 2; jt++) {
                        const int nc = colbase + jt * 8 + g;
                        float v0 = XY[(bs2 + ks + tg) * PADW + nc];
                        float v1 = XY[(bs2 + ks + 4 + tg) * PADW + nc];
                        uint32_t bhv[2], blv[2];
                        bhv[0] = f2tf(v0); blv[0] = f2tf(v0 - __uint_as_float(bhv[0]));
                        bhv[1] = f2tf(v1); blv[1] = f2tf(v1 - __uint_as_float(bhv[1]));
                        mma_tf32(accU[jt], ah, bhv);
                        mma_tf32(accU[jt], ah, blv);
                        mma_tf32(accU[jt], al, bhv);
                    }
                }
#pragma unroll
                for (int jt = 0; jt < 2; jt++) {
                    const int jc = colbase + jt * 8 + 2 * tg;
                    XY[(bs2 + g) * PADW + jc]         = accU[jt][0];
                    XY[(bs2 + g) * PADW + jc + 1]     = accU[jt][1];
                    XY[(bs2 + g + 8) * PADW + jc]     = accU[jt][2];
                    XY[(bs2 + g + 8) * PADW + jc + 1] = accU[jt][3];
                }
                __syncwarp();
            }
        }
    }
    __syncthreads();

    // ---- E: P^T = I - X^T K, R = K^T Y via mma; store all ----
    {
        float aP[4][4], aR[4][4];
#pragma unroll
        for (int jt = 0; jt < 4; jt++)
#pragma unroll
            for (int r = 0; r < 4; r++) { aP[jt][r] = 0.f; aR[jt][r] = 0.f; }
#pragma unroll
        for (int ks = 0; ks < 64; ks += 8) {
            uint32_t ak[4];
            ak[0] = __float_as_uint(kr_t[(ks + tg) * DP + i0]);
            ak[1] = __float_as_uint(kr_t[(ks + tg) * DP + i1]);
            ak[2] = __float_as_uint(kr_t[(ks + 4 + tg) * DP + i0]);
            ak[3] = __float_as_uint(kr_t[(ks + 4 + tg) * DP + i1]);
#pragma unroll
            for (int jt = 0; jt < 4; jt++) {
                const int nc = wn + jt * 8 + g;
                uint32_t bX[2], bY[2];
                bX[0] = f2tf(XY[(ks + tg) * PADW + nc]);
                bX[1] = f2tf(XY[(ks + 4 + tg) * PADW + nc]);
                bY[0] = f2tf(XY[(ks + tg) * PADW + 64 + nc]);
                bY[1] = f2tf(XY[(ks + 4 + tg) * PADW + 64 + nc]);
                mma_tf32(aP[jt], ak, bX);   // (K^T X)[d'][d2]
                mma_tf32(aR[jt], ak, bY);   // (K^T Y)[d'][e]
            }
        }
#pragma unroll
        for (int jt = 0; jt < 4; jt++) {
            const int jc = wn + jt * 8 + 2 * tg;
            gPt[toff + (size_t)(jc    ) * 64 + i0] = ((jc    ) == i0 ? 1.f : 0.f) - aP[jt][0];
            gPt[toff + (size_t)(jc + 1) * 64 + i0] = ((jc + 1) == i0 ? 1.f : 0.f) - aP[jt][1];
            gPt[toff + (size_t)(jc    ) * 64 + i1] = ((jc    ) == i1 ? 1.f : 0.f) - aP[jt][2];
            gPt[toff + (size_t)(jc + 1) * 64 + i1] = ((jc + 1) == i1 ? 1.f : 0.f) - aP[jt][3];
            float2 r0 = make_float2(aR[jt][0], aR[jt][1]);
            float2 r1 = make_float2(aR[jt][2], aR[jt][3]);
            *(float2*)&gR[toff + (size_t)i0 * 64 + jc] = r0;
            *(float2*)&gR[toff + (size_t)i1 * 64 + jc] = r1;
        }
    }
    // ---- store X^T [d][i] and Y [i][e] ----
    {
        const int d  = tid >> 2;
        const int s0 = (tid & 3) << 4;
#pragma unroll
        for (int u = 0; u < 16; u += 4) {
            float4 xv;
            xv.x = XY[(s0 + u + 0) * PADW + d];
            xv.y = XY[(s0 + u + 1) * PADW + d];
            xv.z = XY[(s0 + u + 2) * PADW + d];
            xv.w = XY[(s0 + u + 3) * PADW + d];
            *(float4*)&gXT[toff + (size_t)d * 64 + s0 + u] = xv;
            *(float4*)&gY[toff + (size_t)d * 64 + s0 + u] =
                *(float4*)&XY[d * PADW + 64 + s0 + u];
        }
    }
}

// ================= Phase 2: state scan (96 CTAs, split-tf32 mma) =================
__global__ __launch_bounds__(256) void p2_kernel(
    const float* __restrict__ gPt, const float* __restrict__ gR,
    float* __restrict__ gS)
{
    extern __shared__ float sm[];
    float* S_f = sm;
    float* Sh  = S_f + 64 * DP;
    float* Sl  = Sh  + 64 * DP;
    float* Ph  = Sl  + 64 * DP;
    float* Pl  = Ph  + 64 * DP;

    const int tid  = threadIdx.x;
    const int wid  = tid >> 5;
    const int lane = tid & 31;
    const int wm = (wid & 3) * 16, wn = (wid >> 2) * 32;
    const int g  = lane >> 2,      tg = lane & 3;
    const int i0 = wm + g, i1 = wm + g + 8;

    const int bh = blockIdx.x;
    const int ld  = tid >> 2;
    const int le0 = (tid & 3) << 4;

    for (int i = tid; i < 3 * 64 * DP; i += 256) S_f[i] = 0.f;
    __syncthreads();

    for (int c = 0; c < 64; c++) {
        const size_t toff = ((size_t)bh * 64 + c) * 4096;
#pragma unroll
        for (int u = 0; u < 16; u += 4)
            *(float4*)&gS[toff + (size_t)ld * 64 + le0 + u] = *(float4*)&S_f[ld * DP + le0 + u];
        if (c == 63) break;
#pragma unroll
        for (int u = 0; u < 16; u += 4) {
            float4 p = *(const float4*)&gPt[toff + (size_t)ld * 64 + le0 + u];
            float4 ph, pl;
            ph.x = tfbits(p.x); pl.x = tfbits(p.x - ph.x);
            ph.y = tfbits(p.y); pl.y = tfbits(p.y - ph.y);
            ph.z = tfbits(p.z); pl.z = tfbits(p.z - ph.z);
            ph.w = tfbits(p.w); pl.w = tfbits(p.w - ph.w);
            *(float4*)&Ph[ld * DP + le0 + u] = ph;
            *(float4*)&Pl[ld * DP + le0 + u] = pl;
        }
        __syncthreads();
        float aS[4][4];
#pragma unroll
        for (int jt = 0; jt < 4; jt++)
#pragma unroll
            for (int r = 0; r < 4; r++) aS[jt][r] = 0.f;
#pragma unroll
        for (int ks = 0; ks < 64; ks += 8) {
            uint32_t ah[4], al[4];
            ah[0] = __float_as_uint(Ph[(ks + tg) * DP + i0]);
            ah[1] = __float_as_uint(Ph[(ks + tg) * DP + i1]);
            ah[2] = __float_as_uint(Ph[(ks + 4 + tg) * DP + i0]);
            ah[3] = __float_as_uint(Ph[(ks + 4 + tg) * DP + i1]);
            al[0] = __float_as_uint(Pl[(ks + tg) * DP + i0]);
            al[1] = __float_as_uint(Pl[(ks + tg) * DP + i1]);
            al[2] = __float_as_uint(Pl[(ks + 4 + tg) * DP + i0]);
            al[3] = __float_as_uint(Pl[(ks + 4 + tg) * DP + i1]);
#pragma unroll
            for (int jt = 0; jt < 4; jt++) {
                const int nc = wn + jt * 8 + g;
                uint32_t bh2[2], bl2[2];
                bh2[0] = __float_as_uint(Sh[(ks + tg) * DP + nc]);
                bh2[1] = __float_as_uint(Sh[(ks + 4 + tg) * DP + nc]);
                bl2[0] = __float_as_uint(Sl[(ks + tg) * DP + nc]);
                bl2[1] = __float_as_uint(Sl[(ks + 4 + tg) * DP + nc]);
                mma_tf32(aS[jt], ah, bh2);
                mma_tf32(aS[jt], ah, bl2);
                mma_tf32(aS[jt], al, bh2);
            }
        }
        __syncthreads();
#pragma unroll
        for (int jt = 0; jt < 4; jt++) {
            const int jc = wn + jt * 8 + 2 * tg;
            float2 r0 = *(const float2*)&gR[toff + (size_t)i0 * 64 + jc];
            float2 r1 = *(const float2*)&gR[toff + (size_t)i1 * 64 + jc];
            float s00 = aS[jt][0] + r0.x, s01 = aS[jt][1] + r0.y;
            float s10 = aS[jt][2] + r1.x, s11 = aS[jt][3] + r1.y;
            S_f[i0 * DP + jc] = s00; Sh[i0 * DP + jc] = tfbits(s00);
            Sl[i0 * DP + jc] = tfbits(s00 - tfbits(s00));
            S_f[i0 * DP + jc + 1] = s01; Sh[i0 * DP + jc + 1] = tfbits(s01);
            Sl[i0 * DP + jc + 1] = tfbits(s01 - tfbits(s01));
            S_f[i1 * DP + jc] = s10; Sh[i1 * DP + jc] = tfbits(s10);
            Sl[i1 * DP + jc] = tfbits(s10 - tfbits(s10));
            S_f[i1 * DP + jc + 1] = s11; Sh[i1 * DP + jc + 1] = tfbits(s11);
            Sl[i1 * DP + jc + 1] = tfbits(s11 - tfbits(s11));
        }
        __syncthreads();
    }
}

// ================= Phase 3: per-chunk output (fully parallel) =================
__global__ __launch_bounds__(256) void p3_kernel(
    const float* __restrict__ gq, const float* __restrict__ gk,
    const float* __restrict__ gXT, const float* __restrict__ gYv,
    const float* __restrict__ gS, float* __restrict__ go)
{
    extern __shared__ float sm[];
    float* q_t  = sm;
    float* k_t  = q_t  + 64 * DP;
    float* S_t  = k_t  + 64 * DP;
    float* XT_s = S_t  + 64 * DP;
    float* U_t  = XT_s + 64 * DP;
    float* QK_t = U_t  + 64 * DP;

    const int tid  = threadIdx.x;
    const int wid  = tid >> 5;
    const int lane = tid & 31;
    const int wm = (wid & 3) * 16, wn = (wid >> 2) * 32;
    const int g  = lane >> 2,      tg = lane & 3;
    const int i0 = wm + g, i1 = wm + g + 8;

    const int task = blockIdx.x;
    const int bh = task >> 6, c = task & 63;
    const int b = bh / NH_, h = bh % NH_;
    const size_t base = ((size_t)(b * C_ + h * D_)) * L_ + c * 64;
    const float* qgp = gq + base;
    const float* kgp = gk + base;
    float* ogp = go + base;
    const size_t toff = (size_t)task * 4096;

    const int ld  = tid >> 2;
    const int li0 = (tid & 3) << 4;

    {
        const float* qrow = qgp + (size_t)ld * L_ + li0;
        const float* krow = kgp + (size_t)ld * L_ + li0;
#pragma unroll
        for (int u = 0; u < 16; u += 4) {
            *(float4*)&q_t[ld * DP + li0 + u] = *(const float4*)(qrow + u);
            *(float4*)&k_t[ld * DP + li0 + u] = *(const float4*)(krow + u);
            float4 sv = *(const float4*)&gS[toff + (size_t)ld * 64 + li0 + u];
            float4 xv = *(const float4*)&gXT[toff + (size_t)ld * 64 + li0 + u];
            sv.x = tfbits(sv.x); sv.y = tfbits(sv.y); sv.z = tfbits(sv.z); sv.w = tfbits(sv.w);
            xv.x = tfbits(xv.x); xv.y = tfbits(xv.y); xv.z = tfbits(xv.z); xv.w = tfbits(xv.w);
            *(float4*)&S_t[ld * DP + li0 + u]  = sv;
            *(float4*)&XT_s[ld * DP + li0 + u] = xv;
        }
    }
    __syncthreads();

    {
        const int tok = tid >> 2;
        const int d0  = (tid & 3) << 4;
        float sq = 0.f, sk = 0.f;
#pragma unroll
        for (int d = d0; d < d0 + 16; d++) {
            float qv = q_t[d * DP + tok]; sq += qv * qv;
            float kv = k_t[d * DP + tok]; sk += kv * kv;
        }
        sq += __shfl_xor_sync(0xFFFFFFFFu, sq, 1);
        sq += __shfl_xor_sync(0xFFFFFFFFu, sq, 2);
        sk += __shfl_xor_sync(0xFFFFFFFFu, sk, 1);
        sk += __shfl_xor_sync(0xFFFFFFFFu, sk, 2);
        const float rq = rsqrtf(sq + 1e-6f);
        const float rk = rsqrtf(sk + 1e-6f);
#pragma unroll
        for (int d = d0; d < d0 + 16; d++) {
            q_t[d * DP + tok] = tfbits(q_t[d * DP + tok] * rq);
            k_t[d * DP + tok] = tfbits(k_t[d * DP + tok] * rk);
        }
    }
    __syncthreads();

    {
        float aU[4][4], aQ[4][4];
#pragma unroll
        for (int jt = 0; jt < 4; jt++)
#pragma unroll
            for (int r = 0; r < 4; r++) { aU[jt][r] = 0.f; aQ[jt][r] = 0.f; }
#pragma unroll
        for (int ks = 0; ks < 64; ks += 8) {
            uint32_t ax[4], aq[4];
            ax[0] = __float_as_uint(XT_s[(ks + tg) * DP + i0]);
            ax[1] = __float_as_uint(XT_s[(ks + tg) * DP + i1]);
            ax[2] = __float_as_uint(XT_s[(ks + 4 + tg) * DP + i0]);
            ax[3] = __float_as_uint(XT_s[(ks + 4 + tg) * DP + i1]);
            aq[0] = __float_as_uint(q_t[(ks + tg) * DP + i0]);
            aq[1] = __float_as_uint(q_t[(ks + tg) * DP + i1]);
            aq[2] = __float_as_uint(q_t[(ks + 4 + tg) * DP + i0]);
            aq[3] = __float_as_uint(q_t[(ks + 4 + tg) * DP + i1]);
#pragma unroll
            for (int jt = 0; jt < 4; jt++) {
                const int nc = wn + jt * 8 + g;
                uint32_t bS[2], bk[2];
                bS[0] = __float_as_uint(S_t[(ks + tg) * DP + nc]);
                bS[1] = __float_as_uint(S_t[(ks + 4 + tg) * DP + nc]);
                bk[0] = __float_as_uint(k_t[(ks + tg) * DP + nc]);
                bk[1] = __float_as_uint(k_t[(ks + 4 + tg) * DP + nc]);
                mma_tf32(aU[jt], ax, bS);
                mma_tf32(aQ[jt], aq, bk);
            }
        }
#pragma unroll
        for (int jt = 0; jt < 4; jt++) {
            const int jc = wn + jt * 8 + 2 * tg;
            float2 y0 = *(const float2*)&gYv[toff + (size_t)i0 * 64 + jc];
            float2 y1 = *(const float2*)&gYv[toff + (size_t)i1 * 64 + jc];
            U_t[i0 * DP + jc]     = tfbits(y0.x - aU[jt][0]);
            U_t[i0 * DP + jc + 1] = tfbits(y0.y - aU[jt][1]);
            U_t[i1 * DP + jc]     = tfbits(y1.x - aU[jt][2]);
            U_t[i1 * DP + jc + 1] = tfbits(y1.y - aU[jt][3]);
            QK_t[jc * DP + i0]       = tfbits((jc     <= i0) ? aQ[jt][0] : 0.f);
            QK_t[(jc + 1) * DP + i0] = tfbits((jc + 1 <= i0) ? aQ[jt][1] : 0.f);
            QK_t[jc * DP + i1]       = tfbits((jc     <= i1) ? aQ[jt][2] : 0.f);
            QK_t[(jc + 1) * DP + i1] = tfbits((jc + 1 <= i1) ? aQ[jt][3] : 0.f);
        }
    }
    __syncthreads();

    {
        float aO[4][4];
#pragma unroll
        for (int jt = 0; jt < 4; jt++)
#pragma unroll
            for (int r = 0; r < 4; r++) aO[jt][r] = 0.f;
#pragma unroll
        for (int ks = 0; ks < 64; ks += 8) {
            uint32_t aq[4], a2[4];
            aq[0] = __float_as_uint(q_t[(ks + tg) * DP + i0]);
            aq[1] = __float_as_uint(q_t[(ks + tg) * DP + i1]);
            aq[2] = __float_as_uint(q_t[(ks + 4 + tg) * DP + i0]);
            aq[3] = __float_as_uint(q_t[(ks + 4 + tg) * DP + i1]);
            a2[0] = __float_as_uint(QK_t[(ks + tg) * DP + i0]);
            a2[1] = __float_as_uint(QK_t[(ks + tg) * DP + i1]);
            a2[2] = __float_as_uint(QK_t[(ks + 4 + tg) * DP + i0]);
            a2[3] = __float_as_uint(QK_t[(ks + 4 + tg) * DP + i1]);
#pragma unroll
            for (int jt = 0; jt < 4; jt++) {
                const int nc = wn + jt * 8 + g;
                uint32_t bS[2], bU[2];
                bS[0] = __float_as_uint(S_t[(ks + tg) * DP + nc]);
                bS[1] = __float_as_uint(S_t[(ks + 4 + tg) * DP + nc]);
                bU[0] = __float_as_uint(U_t[(ks + tg) * DP + nc]);
                bU[1] = __float_as_uint(U_t[(ks + 4 + tg) * DP + nc]);
                mma_tf32(aO[jt], aq, bS);
                mma_tf32(aO[jt], a2, bU);
            }
        }
        __syncthreads();
#pragma unroll
        for (int jt = 0; jt < 4; jt++) {
            const int ec = wn + jt * 8 + 2 * tg;
            k_t[ec * DP + i0]       = aO[jt][0];
            k_t[(ec + 1) * DP + i0] = aO[jt][1];
            k_t[ec * DP + i1]       = aO[jt][2];
            k_t[(ec + 1) * DP + i1] = aO[jt][3];
        }
    }
    __syncthreads();

    {
        float* dst = ogp + (size_t)ld * L_ + li0;
#pragma unroll
        for (int u = 0; u < 16; u += 4)
            *(float4*)(dst + u) = *(float4*)&k_t[ld * DP + li0 + u];
    }
}

// ---------------- launch ----------------
extern "C" void kernel_launch(void* const* d_in, const int* in_sizes, int n_in,
                              void* d_out, int out_size)
{
    const float* x  = (const float*)d_in[0];
    const float* Wq = (const float*)d_in[1];
    const float* Wk = (const float*)d_in[2];
    const float* Wv = (const float*)d_in[3];
    const float* Wb = (const float*)d_in[4];
    const float* Wo = (const float*)d_in[5];
    float* out = (float*)d_out;

    float *qp, *kp, *vp, *op, *bp, *xtp, *yp, *ptp, *rp, *sp;
    cudaGetSymbolAddress((void**)&qp, g_q);
    cudaGetSymbolAddress((void**)&kp, g_k);
    cudaGetSymbolAddress((void**)&vp, g_v);
    cudaGetSymbolAddress((void**)&op, g_o);
    cudaGetSymbolAddress((void**)&bp, g_beta);
    cudaGetSymbolAddress((void**)&xtp, g_XT);
    cudaGetSymbolAddress((void**)&yp, g_Y);
    cudaGetSymbolAddress((void**)&ptp, g_Pt);
    cudaGetSymbolAddress((void**)&rp, g_R);
    cudaGetSymbolAddress((void**)&sp, g_S);

    const int smemP1 = (3 * 64 * DP + 64 * PADW + 16 * DP + 64) * (int)sizeof(float);
    const int smemP2 = (5 * 64 * DP) * (int)sizeof(float);
    const int smemP3 = (6 * 64 * DP) * (int)sizeof(float);
    cudaFuncSetAttribute(p1_kernel, cudaFuncAttributeMaxDynamicSharedMemorySize, smemP1);
    cudaFuncSetAttribute(p2_kernel, cudaFuncAttributeMaxDynamicSharedMemorySize, smemP2);
    cudaFuncSetAttribute(p3_kernel, cudaFuncAttributeMaxDynamicSharedMemorySize, smemP3);

    dim3 blk(256);
    beta_kernel<<<128, blk>>>(x, Wb, bp);
    gemm_tf32<0, 2><<<dim3(256, 6, 2), blk>>>(x, Wq, Wk, nullptr, nullptr, qp, kp, nullptr);
    gemm_tf32<0, 1><<<dim3(256, 6, 1), blk>>>(x, Wv, nullptr, nullptr, nullptr, vp, nullptr, nullptr);
    p1_kernel<<<NT_, blk, smemP1>>>(kp, vp, bp, xtp, yp, ptp, rp);
    p2_kernel<<<BH_, blk, smemP2>>>(ptp, rp, sp);
    p3_kernel<<<NT_, blk, smemP3>>>(qp, kp, xtp, yp, sp, op);
    gemm_tf32<1, 1><<<dim3(256, 6, 1), blk>>>(op, Wo, nullptr, nullptr, x, out, nullptr, nullptr);
}